// round 1
// baseline (speedup 1.0000x reference)
#include <cuda_runtime.h>
#include <cstdint>

// Problem constants
#define C64   64
#define NSEQ  16384
#define MTOT  65536          // B*N = 4*16384
#define EPSV  1e-5f

// Scratch (device globals -- no allocation allowed)
__device__ float g_Wt[64 * 64 * 64];   // [k][j][i] : transposed Wx, 1 MB
__device__ float g_bias[64 * 64];      // [k][i]    : cm @ Wcm

// packed fp32x2 FMA (Blackwell f32x2 pipe, 2x FFMA throughput)
__device__ __forceinline__ void fma2(float2 &d, const float2 &a, const float2 &b) {
    asm("fma.rn.f32x2 %0, %1, %2, %0;"
        : "+l"(*reinterpret_cast<unsigned long long *>(&d))
        : "l"(*reinterpret_cast<const unsigned long long *>(&a)),
          "l"(*reinterpret_cast<const unsigned long long *>(&b)));
}

// ---------------------------------------------------------------------------
// Prep: transpose Wx into g_Wt[k][j][i], compute bias[k][i] = sum_j cm[k][j]*Wcm[k][i][j]
// 64 blocks (one per k) x 256 threads. Runs once per launch; ~microseconds.
// ---------------------------------------------------------------------------
__global__ void prep_kernel(const float *__restrict__ W, const float *__restrict__ cm) {
    const int k   = blockIdx.x;
    const int tid = threadIdx.x;
    const float *Wk = W + k * 64 * 128;

    // transpose Wx: g_Wt[(k*64 + j)*64 + i] = W[k][i][j]  (j < 64)
#pragma unroll
    for (int t = 0; t < 16; ++t) {
        int e = tid + t * 256;        // 0..4095
        int j = e >> 6, i = e & 63;
        g_Wt[(k * 64 + j) * 64 + i] = Wk[i * 128 + j];
    }

    // bias
    if (tid < 64) {
        const int i = tid;
        const float *cmk = cm + k * 64;
        float s = 0.f;
#pragma unroll 8
        for (int j = 0; j < 64; ++j)
            s = fmaf(cmk[j], Wk[i * 128 + 64 + j], s);
        g_bias[k * 64 + i] = s;
    }
}

// ---------------------------------------------------------------------------
// Main: block tile = 64 m-rows x 256 out-cols (4 k's x 64 i).
// 256 threads: warp ti owns 8 m-rows, lanes span i (2 i's per lane, packed f32x2).
// Fused: GEMM + bias + clip + warp-allreduce L1 normalization + coalesced store.
// ---------------------------------------------------------------------------
__global__ __launch_bounds__(256, 2)
void sig_kernel(const float *__restrict__ x, float *__restrict__ out) {
    extern __shared__ char smem[];
    float2 *xs = reinterpret_cast<float2 *>(smem);            // [64 j][64 m] dup pairs : 32 KB
    float  *ws = reinterpret_cast<float *>(smem + 32768);     // [4 kl][64 j][64 i]     : 64 KB
    float  *bs = reinterpret_cast<float *>(smem + 32768 + 65536); // [256]              : 1 KB

    const int tid  = threadIdx.x;
    const int lane = tid & 31;
    const int ti   = tid >> 5;          // warp id 0..7 -> m sub-tile
    const int mt   = blockIdx.x;        // 0..1023 (m tile of 64)
    const int kg   = blockIdx.y;        // 0..15   (k group of 4)

    const int m0 = mt * 64;
    const int b  = m0 >> 14;            // / 16384
    const int n0 = m0 & (NSEQ - 1);
    const float *xb = x + (size_t)b * C64 * NSEQ + n0;

    // --- load W tile: straight float4 copy of g_Wt slice (layout identical) ---
    {
        const float4 *src = reinterpret_cast<const float4 *>(g_Wt + kg * 16384);
        float4 *dst = reinterpret_cast<float4 *>(ws);
#pragma unroll
        for (int t = 0; t < 16; ++t)
            dst[tid + t * 256] = src[tid + t * 256];
    }
    // --- load x tile, duplicated into float2 (so fma2 gets (x,x) operand free) ---
#pragma unroll
    for (int t = 0; t < 4; ++t) {
        int e = tid + t * 256;          // float4 index 0..1023
        int j = e >> 4, c = e & 15;
        float4 v = *reinterpret_cast<const float4 *>(xb + (size_t)j * NSEQ + c * 4);
        float2 *d = xs + j * 64 + c * 4;
        d[0] = make_float2(v.x, v.x);
        d[1] = make_float2(v.y, v.y);
        d[2] = make_float2(v.z, v.z);
        d[3] = make_float2(v.w, v.w);
    }
    bs[tid] = g_bias[kg * 256 + tid];
    __syncthreads();

    // --- K loop: acc[rm][kl] covers (m = m0+ti*8+rm, i = 2*lane, 2*lane+1 of k = kg*4+kl)
    float2 acc[8][4];
#pragma unroll
    for (int rm = 0; rm < 8; ++rm)
#pragma unroll
        for (int kl = 0; kl < 4; ++kl)
            acc[rm][kl] = make_float2(0.f, 0.f);

#pragma unroll 4
    for (int j = 0; j < 64; ++j) {
        float2 wv[4];
#pragma unroll
        for (int kl = 0; kl < 4; ++kl)   // lane-contiguous LDS.64, conflict-free
            wv[kl] = *reinterpret_cast<const float2 *>(ws + kl * 4096 + j * 64 + 2 * lane);
        float2 xv[8];
#pragma unroll
        for (int rm = 0; rm < 8; ++rm)   // broadcast LDS.64
            xv[rm] = xs[j * 64 + ti * 8 + rm];
#pragma unroll
        for (int rm = 0; rm < 8; ++rm)
#pragma unroll
            for (int kl = 0; kl < 4; ++kl)
                fma2(acc[rm][kl], xv[rm], wv[kl]);
    }

    // --- epilogue: bias + clip + warp L1-normalize over i + coalesced store ---
    float2 bias2[4];
#pragma unroll
    for (int kl = 0; kl < 4; ++kl)
        bias2[kl] = *reinterpret_cast<const float2 *>(bs + kl * 64 + 2 * lane);

    const float HI = 1.0f - 1e-5f;
#pragma unroll
    for (int rm = 0; rm < 8; ++rm) {
        const int m = m0 + ti * 8 + rm;
        float *orow = out + (size_t)m * 4096 + kg * 256;
#pragma unroll
        for (int kl = 0; kl < 4; ++kl) {
            float vx = fminf(fmaxf(acc[rm][kl].x + bias2[kl].x, EPSV), HI);
            float vy = fminf(fmaxf(acc[rm][kl].y + bias2[kl].y, EPSV), HI);
            float ps = vx + vy;               // lanes span the 64 i's (2 each)
#pragma unroll
            for (int o = 16; o > 0; o >>= 1)
                ps += __shfl_xor_sync(0xffffffffu, ps, o);
            float inv = __fdividef(1.0f, ps); // values all >= 64*EPS > 0
            *reinterpret_cast<float2 *>(orow + kl * 64 + 2 * lane) =
                make_float2(vx * inv, vy * inv);
        }
    }
}

// ---------------------------------------------------------------------------
extern "C" void kernel_launch(void *const *d_in, const int *in_sizes, int n_in,
                              void *d_out, int out_size) {
    const float *x  = (const float *)d_in[0];   // (4, 64, 16384) f32
    const float *cm = (const float *)d_in[1];   // (64, 64) f32
    const float *W  = (const float *)d_in[2];   // (64, 64, 128) f32
    float *out = (float *)d_out;                // (65536, 64, 64) f32

    (void)in_sizes; (void)n_in; (void)out_size;

    const int smem_bytes = 32768 + 65536 + 1024;   // 99,328 B
    cudaFuncSetAttribute(sig_kernel, cudaFuncAttributeMaxDynamicSharedMemorySize, smem_bytes);

    prep_kernel<<<64, 256>>>(W, cm);
    dim3 grid(1024, 16);
    sig_kernel<<<grid, 256, smem_bytes>>>(x, out);
}